// round 1
// baseline (speedup 1.0000x reference)
#include <cuda_runtime.h>
#include <cuda_bf16.h>
#include <math.h>

// Problem constants (fixed shapes for this problem instance)
#define BATCH   8
#define SPTS    2048      // S
#define NPTS    8192      // N
#define FDIM    256       // F (super point feature dim)
#define CDIM    128       // C (point feature dim)
#define DIN     384       // C + F
#define DH      512
#define DOUT    512
#define MROWS   (BATCH * NPTS)          // 65536
#define EPSF    1.1920929e-07f          // np.finfo(float32).eps
#define BN_EPS  1e-5f

// ---------------- scratch (device globals; no dynamic allocation) ----------
__device__ float g_X[(size_t)MROWS * DIN];     // concat(point_features, interp)  96 MB
__device__ float g_H[(size_t)MROWS * DH];      // hidden after GEMM1             134 MB
__device__ float g_part[128 * 512 * 2];        // per-block partial col sums
__device__ float g_stats[2 * 512 * 2];         // [layer][sum(512) | sumsq(512)]

// ======================= kernel 1: 3-NN interpolation ======================
// grid (NPTS/256, BATCH), block 256
__global__ __launch_bounds__(256)
void interp_kernel(const float* __restrict__ sxyz_g,
                   const float* __restrict__ spf,
                   const float* __restrict__ xyz,
                   const float* __restrict__ pf)
{
    __shared__ float sx[SPTS], sy[SPTS], sz[SPTS], sn2[SPTS];
    __shared__ int   s_idx[256][3];
    __shared__ float s_w[256][3];

    const int b   = blockIdx.y;
    const int tid = threadIdx.x;

    // cooperative load of super_xyz[b] (2048 x 3)
    const float* sb = sxyz_g + (size_t)b * SPTS * 3;
    for (int j = tid; j < SPTS * 3; j += 256) {
        float v = sb[j];
        int s = j / 3, c = j - 3 * s;
        if      (c == 0) sx[s] = v;
        else if (c == 1) sy[s] = v;
        else             sz[s] = v;
    }
    __syncthreads();
    for (int s = tid; s < SPTS; s += 256)
        sn2[s] = sx[s]*sx[s] + sy[s]*sy[s] + sz[s]*sz[s];
    __syncthreads();

    // one point per thread: scan all super points, keep top-3 smallest d2
    const int p  = blockIdx.x * 256 + tid;
    const int gp = b * NPTS + p;
    const float px = xyz[(size_t)gp*3 + 0];
    const float py = xyz[(size_t)gp*3 + 1];
    const float pz = xyz[(size_t)gp*3 + 2];
    const float n1 = px*px + py*py + pz*pz;

    float d0 = 3.4e38f, d1 = 3.4e38f, d2 = 3.4e38f;
    int   i0 = 0, i1 = 0, i2 = 0;

    #pragma unroll 4
    for (int s = 0; s < SPTS; ++s) {
        float dot = sx[s]*px + sy[s]*py + sz[s]*pz;
        float d   = -2.0f*dot + n1 + sn2[s];   // reference's expanded form & order
        if (d < d2) {
            if (d < d1) {
                d2 = d1; i2 = i1;
                if (d < d0) { d1 = d0; i1 = i0; d0 = d; i0 = s; }
                else        { d1 = d;  i1 = s; }
            } else { d2 = d; i2 = s; }
        }
    }

    float w0 = 1.0f / (fmaxf(d0, 0.0f) + EPSF);
    float w1 = 1.0f / (fmaxf(d1, 0.0f) + EPSF);
    float w2 = 1.0f / (fmaxf(d2, 0.0f) + EPSF);
    float inv = 1.0f / (w0 + w1 + w2);
    s_idx[tid][0] = i0; s_idx[tid][1] = i1; s_idx[tid][2] = i2;
    s_w[tid][0] = w0 * inv; s_w[tid][1] = w1 * inv; s_w[tid][2] = w2 * inv;
    __syncthreads();

    // warp-cooperative gather + concat write (coalesced float4)
    const int warp = tid >> 5, lane = tid & 31;
    for (int q = warp; q < 256; q += 8) {
        const int pp   = blockIdx.x * 256 + q;
        const int grow = b * NPTS + pp;
        const float4* r0 = (const float4*)(spf + ((size_t)b*SPTS + s_idx[q][0]) * FDIM);
        const float4* r1 = (const float4*)(spf + ((size_t)b*SPTS + s_idx[q][1]) * FDIM);
        const float4* r2 = (const float4*)(spf + ((size_t)b*SPTS + s_idx[q][2]) * FDIM);
        const float a0 = s_w[q][0], a1 = s_w[q][1], a2 = s_w[q][2];
        float4* out = (float4*)(g_X + (size_t)grow * DIN);

        // copy point_features (128 floats = 32 float4)
        const float4* pr = (const float4*)(pf + (size_t)grow * CDIM);
        out[lane] = pr[lane];

        // interp (256 floats = 64 float4), lanes cover c4 = lane and lane+32
        #pragma unroll
        for (int h = 0; h < 2; ++h) {
            int c4 = lane + h * 32;
            float4 va = r0[c4], vb = r1[c4], vc = r2[c4];
            float4 o;
            o.x = a0*va.x + a1*vb.x + a2*vc.x;
            o.y = a0*va.y + a1*vb.y + a2*vc.y;
            o.z = a0*va.z + a1*vb.z + a2*vc.z;
            o.w = a0*va.w + a1*vb.w + a2*vc.w;
            out[32 + c4] = o;
        }
    }
}

// ======================= kernel 2: fp32 SGEMM ==============================
// C[M,N] = A[M,K] @ B[K,N], all row-major. M%128==0, N%128==0, K%16==0.
// 128x128 block tile, BK=16, 256 threads, 8x8 per thread.
__global__ __launch_bounds__(256)
void sgemm_kernel(const float* __restrict__ A, const float* __restrict__ B,
                  float* __restrict__ C, int M, int N, int K)
{
    const int BM = 128, BN = 128, BK = 16, TM = 8, TN = 8;
    __shared__ float As[BK][BM];
    __shared__ float Bs[BK][BN];

    const int tid = threadIdx.x;
    const int aRow  = tid >> 2;          // 0..63
    const int aCol4 = tid & 3;           // float4 column in A tile
    const int bRow  = tid >> 5;          // 0..7
    const int bCol4 = tid & 31;          // float4 column in B tile
    const int tr = (tid >> 4) * TM;      // 0..120
    const int tc = (tid & 15) * TN;      // 0..120

    const float* Ab = A + (size_t)blockIdx.y * BM * K;
    const float* Bb = B + (size_t)blockIdx.x * BN;

    float acc[TM][TN];
    #pragma unroll
    for (int i = 0; i < TM; ++i)
        #pragma unroll
        for (int j = 0; j < TN; ++j) acc[i][j] = 0.0f;

    for (int kt = 0; kt < K; kt += BK) {
        #pragma unroll
        for (int i = 0; i < 2; ++i) {
            int r = aRow + i * 64;
            float4 v = *(const float4*)(Ab + (size_t)r * K + kt + aCol4 * 4);
            As[aCol4*4 + 0][r] = v.x;
            As[aCol4*4 + 1][r] = v.y;
            As[aCol4*4 + 2][r] = v.z;
            As[aCol4*4 + 3][r] = v.w;
        }
        #pragma unroll
        for (int i = 0; i < 2; ++i) {
            int r = bRow + i * 8;
            float4 v = *(const float4*)(Bb + (size_t)(kt + r) * N + bCol4 * 4);
            *(float4*)&Bs[r][bCol4 * 4] = v;
        }
        __syncthreads();

        #pragma unroll
        for (int k = 0; k < BK; ++k) {
            float af[TM], bf[TN];
            #pragma unroll
            for (int i = 0; i < TM; ++i) af[i] = As[k][tr + i];
            #pragma unroll
            for (int j = 0; j < TN; ++j) bf[j] = Bs[k][tc + j];
            #pragma unroll
            for (int i = 0; i < TM; ++i)
                #pragma unroll
                for (int j = 0; j < TN; ++j)
                    acc[i][j] = fmaf(af[i], bf[j], acc[i][j]);
        }
        __syncthreads();
    }

    float* Cb = C + (size_t)(blockIdx.y * BM + tr) * N + blockIdx.x * BN + tc;
    #pragma unroll
    for (int i = 0; i < TM; ++i) {
        *(float4*)(Cb + (size_t)i * N + 0) = make_float4(acc[i][0], acc[i][1], acc[i][2], acc[i][3]);
        *(float4*)(Cb + (size_t)i * N + 4) = make_float4(acc[i][4], acc[i][5], acc[i][6], acc[i][7]);
    }
}

// =================== kernel 3: column stats (deterministic 2-stage) ========
// stage 1: 128 blocks x 512 threads; block b reduces rows [b*512,(b+1)*512)
__global__ __launch_bounds__(512)
void colstats_partial(const float* __restrict__ H)
{
    const int c = threadIdx.x;
    const int blk = blockIdx.x;
    float s = 0.0f, q = 0.0f;
    const size_t base = (size_t)blk * 512 * 512;
    #pragma unroll 4
    for (int r = 0; r < 512; ++r) {
        float v = H[base + (size_t)r * 512 + c];
        s += v;
        q += v * v;
    }
    g_part[(size_t)blk * 1024 + c]       = s;
    g_part[(size_t)blk * 1024 + 512 + c] = q;
}

// stage 2: 1 block x 512 threads -> g_stats[layer]
__global__ __launch_bounds__(512)
void colstats_final(int layer)
{
    const int c = threadIdx.x;
    float s = 0.0f, q = 0.0f;
    for (int b = 0; b < 128; ++b) {
        s += g_part[(size_t)b * 1024 + c];
        q += g_part[(size_t)b * 1024 + 512 + c];
    }
    g_stats[(size_t)layer * 1024 + c]       = s;
    g_stats[(size_t)layer * 1024 + 512 + c] = q;
}

// =================== kernel 4: BN (training) + exact GELU, in place ========
__global__ __launch_bounds__(256)
void bn_gelu_kernel(float* __restrict__ H,
                    const float* __restrict__ gamma,
                    const float* __restrict__ beta,
                    int layer)
{
    const size_t idx = (size_t)blockIdx.x * blockDim.x + threadIdx.x;  // float4 idx
    const size_t total = (size_t)MROWS * 512 / 4;
    if (idx >= total) return;
    const int c0 = (int)((idx & 127) * 4);   // 128 float4 per row
    const float invM = 1.0f / (float)MROWS;
    const float* st = g_stats + (size_t)layer * 1024;

    float4 v = ((const float4*)H)[idx];
    float o[4] = {v.x, v.y, v.z, v.w};
    #pragma unroll
    for (int j = 0; j < 4; ++j) {
        int c = c0 + j;
        float m   = st[c] * invM;
        float var = st[512 + c] * invM - m * m;
        float inv = rsqrtf(var + BN_EPS);
        float y   = (o[j] - m) * inv * gamma[c] + beta[c];
        o[j] = 0.5f * y * (1.0f + erff(y * 0.70710678118654752f));
    }
    ((float4*)H)[idx] = make_float4(o[0], o[1], o[2], o[3]);
}

// ============================ launcher =====================================
extern "C" void kernel_launch(void* const* d_in, const int* in_sizes, int n_in,
                              void* d_out, int out_size)
{
    const float* sxyz = (const float*)d_in[0];
    const float* spf  = (const float*)d_in[1];
    const float* xyz  = (const float*)d_in[2];
    const float* pf   = (const float*)d_in[3];
    const float* W1   = (const float*)d_in[4];
    const float* g1   = (const float*)d_in[5];
    const float* b1   = (const float*)d_in[6];
    const float* W2   = (const float*)d_in[7];
    const float* g2   = (const float*)d_in[8];
    const float* b2   = (const float*)d_in[9];
    float* out = (float*)d_out;

    float *pX = nullptr, *pH = nullptr;
    cudaGetSymbolAddress((void**)&pX, g_X);
    cudaGetSymbolAddress((void**)&pH, g_H);

    // 1) 3-NN interpolation + concat -> g_X [65536, 384]
    interp_kernel<<<dim3(NPTS / 256, BATCH), 256>>>(sxyz, spf, xyz, pf);

    // 2) GEMM1: g_X @ W1 -> g_H [65536, 512]
    sgemm_kernel<<<dim3(DH / 128, MROWS / 128), 256>>>(pX, W1, pH, MROWS, DH, DIN);

    // 3) BN stats layer 1 (deterministic) + BN+GELU in place on g_H
    colstats_partial<<<128, 512>>>(pH);
    colstats_final<<<1, 512>>>(0);
    bn_gelu_kernel<<<(MROWS * 512 / 4 + 255) / 256, 256>>>(pH, g1, b1, 0);

    // 4) GEMM2: g_H @ W2 -> d_out [65536, 512]
    sgemm_kernel<<<dim3(DOUT / 128, MROWS / 128), 256>>>(pH, W2, out, MROWS, DOUT, DH);

    // 5) BN stats layer 2 + BN+GELU in place on d_out
    colstats_partial<<<128, 512>>>(out);
    colstats_final<<<1, 512>>>(1);
    bn_gelu_kernel<<<(MROWS * 512 / 4 + 255) / 256, 256>>>(out, g2, b2, 1);
}

// round 3
// speedup vs baseline: 1.5342x; 1.5342x over previous
#include <cuda_runtime.h>
#include <cuda_fp16.h>
#include <math.h>
#include <stdint.h>

// Problem constants
#define BATCH   8
#define SPTS    2048
#define NPTS    8192
#define FDIM    256
#define CDIM    128
#define DIN     384
#define DH      512
#define DOUT    512
#define MROWS   (BATCH * NPTS)          // 65536
#define EPSF    1.1920929e-07f
#define BN_EPS  1e-5f

#define K1P     (3 * DIN)               // 1152
#define K2P     (3 * DH)                // 1536

// ---------------- scratch (device globals) ---------------------------------
__device__ __half g_A1[(size_t)MROWS * K1P];   // split X    151 MB
__device__ __half g_A2[(size_t)MROWS * K2P];   // split H'   201 MB
__device__ __half g_B1[(size_t)DH  * K1P];     // split W1^T 1.2 MB
__device__ __half g_B2[(size_t)DOUT * K2P];    // split W2^T 1.6 MB
__device__ float g_H[(size_t)MROWS * DH];      // GEMM1 out  134 MB
__device__ float g_part[128 * 512 * 2];
__device__ float g_stats[2 * 512 * 2];

// hi/lo fp16 split write: row[c..c+3]=hi, row[seg+c..]=lo, row[2seg+c..]=hi
__device__ __forceinline__ void wsplit4(__half* row, int seg, int c, float4 v) {
    float a[4] = {v.x, v.y, v.z, v.w};
    __half h[4], l[4];
    #pragma unroll
    for (int j = 0; j < 4; ++j) {
        h[j] = __float2half_rn(a[j]);
        l[j] = __float2half_rn(a[j] - __half2float(h[j]));
    }
    __half2* p0 = (__half2*)(row + c);
    __half2* p1 = (__half2*)(row + seg + c);
    __half2* p2 = (__half2*)(row + 2 * seg + c);
    p0[0] = __halves2half2(h[0], h[1]); p0[1] = __halves2half2(h[2], h[3]);
    p1[0] = __halves2half2(l[0], l[1]); p1[1] = __halves2half2(l[2], l[3]);
    p2[0] = __halves2half2(h[0], h[1]); p2[1] = __halves2half2(h[2], h[3]);
}

// ======================= kernel 1: 3-NN interpolation ======================
__global__ __launch_bounds__(256)
void interp_kernel(const float* __restrict__ sxyz_g,
                   const float* __restrict__ spf,
                   const float* __restrict__ xyz,
                   const float* __restrict__ pf)
{
    __shared__ float sx[SPTS], sy[SPTS], sz[SPTS], sn2[SPTS];
    __shared__ int   s_idx[256][3];
    __shared__ float s_w[256][3];

    const int b   = blockIdx.y;
    const int tid = threadIdx.x;

    const float* sb = sxyz_g + (size_t)b * SPTS * 3;
    for (int j = tid; j < SPTS * 3; j += 256) {
        float v = sb[j];
        int s = j / 3, c = j - 3 * s;
        if      (c == 0) sx[s] = v;
        else if (c == 1) sy[s] = v;
        else             sz[s] = v;
    }
    __syncthreads();
    for (int s = tid; s < SPTS; s += 256)
        sn2[s] = sx[s]*sx[s] + sy[s]*sy[s] + sz[s]*sz[s];
    __syncthreads();

    const int p  = blockIdx.x * 256 + tid;
    const int gp = b * NPTS + p;
    const float px = xyz[(size_t)gp*3 + 0];
    const float py = xyz[(size_t)gp*3 + 1];
    const float pz = xyz[(size_t)gp*3 + 2];
    const float n1 = px*px + py*py + pz*pz;

    float d0 = 3.4e38f, d1 = 3.4e38f, d2 = 3.4e38f;
    int   i0 = 0, i1 = 0, i2 = 0;

    #pragma unroll 4
    for (int s = 0; s < SPTS; ++s) {
        float dot = sx[s]*px + sy[s]*py + sz[s]*pz;
        float d   = -2.0f*dot + n1 + sn2[s];
        if (d < d2) {
            if (d < d1) {
                d2 = d1; i2 = i1;
                if (d < d0) { d1 = d0; i1 = i0; d0 = d; i0 = s; }
                else        { d1 = d;  i1 = s; }
            } else { d2 = d; i2 = s; }
        }
    }

    float w0 = 1.0f / (fmaxf(d0, 0.0f) + EPSF);
    float w1 = 1.0f / (fmaxf(d1, 0.0f) + EPSF);
    float w2 = 1.0f / (fmaxf(d2, 0.0f) + EPSF);
    float inv = 1.0f / (w0 + w1 + w2);
    s_idx[tid][0] = i0; s_idx[tid][1] = i1; s_idx[tid][2] = i2;
    s_w[tid][0] = w0 * inv; s_w[tid][1] = w1 * inv; s_w[tid][2] = w2 * inv;
    __syncthreads();

    const int warp = tid >> 5, lane = tid & 31;
    for (int q = warp; q < 256; q += 8) {
        const int pp   = blockIdx.x * 256 + q;
        const int grow = b * NPTS + pp;
        const float4* r0 = (const float4*)(spf + ((size_t)b*SPTS + s_idx[q][0]) * FDIM);
        const float4* r1 = (const float4*)(spf + ((size_t)b*SPTS + s_idx[q][1]) * FDIM);
        const float4* r2 = (const float4*)(spf + ((size_t)b*SPTS + s_idx[q][2]) * FDIM);
        const float a0 = s_w[q][0], a1 = s_w[q][1], a2 = s_w[q][2];
        __half* arow = g_A1 + (size_t)grow * K1P;

        const float4 pr4 = ((const float4*)(pf + (size_t)grow * CDIM))[lane];
        wsplit4(arow, DIN, lane * 4, pr4);

        #pragma unroll
        for (int h = 0; h < 2; ++h) {
            int c4 = lane + h * 32;
            float4 va = r0[c4], vb = r1[c4], vc = r2[c4];
            float4 o;
            o.x = a0*va.x + a1*vb.x + a2*vc.x;
            o.y = a0*va.y + a1*vb.y + a2*vc.y;
            o.z = a0*va.z + a1*vb.z + a2*vc.z;
            o.w = a0*va.w + a1*vb.w + a2*vc.w;
            wsplit4(arow, DIN, CDIM + c4 * 4, o);
        }
    }
}

// ============== kernel 1b: split + transpose weights =======================
// W [K, N] row-major -> B'[N, 3K]: seg0 = hi, seg1 = hi, seg2 = lo
__global__ __launch_bounds__(256)
void wsplit_kernel(const float* __restrict__ W, __half* __restrict__ Bp,
                   int K, int N)
{
    int i = blockIdx.x * 256 + threadIdx.x;
    if (i >= K * N) return;
    int n = i % N, k = i / N;
    float w = W[(size_t)k * N + n];
    __half h = __float2half_rn(w);
    __half l = __float2half_rn(w - __half2float(h));
    __half* row = Bp + (size_t)n * 3 * K;
    row[k]         = h;
    row[K + k]     = h;
    row[2 * K + k] = l;
}

// ======================= kernel 2: HMMA fp16 GEMM ==========================
// C[M,N] = A'[M,Kp] . B'[N,Kp]^T  (both K-major fp16), fp32 accumulate.
// CTA tile 128x128, BK=32, 8 warps (4x2), warp tile 32x64, m16n8k16.
// smem row stride 40 halves (80B, odd multiple of 16B) -> ldmatrix conflict-free.
#define LDSTR 40

__device__ __forceinline__ void ldsm4(uint32_t* r, uint32_t addr) {
    asm volatile("ldmatrix.sync.aligned.m8n8.x4.shared.b16 {%0,%1,%2,%3}, [%4];"
                 : "=r"(r[0]), "=r"(r[1]), "=r"(r[2]), "=r"(r[3]) : "r"(addr));
}
__device__ __forceinline__ void mma16816(float* c, const uint32_t* a,
                                         uint32_t b0, uint32_t b1) {
    asm volatile(
        "mma.sync.aligned.m16n8k16.row.col.f32.f16.f16.f32 "
        "{%0,%1,%2,%3}, {%4,%5,%6,%7}, {%8,%9}, {%0,%1,%2,%3};"
        : "+f"(c[0]), "+f"(c[1]), "+f"(c[2]), "+f"(c[3])
        : "r"(a[0]), "r"(a[1]), "r"(a[2]), "r"(a[3]), "r"(b0), "r"(b1));
}
#define CPASYNC16(dst, src) \
    asm volatile("cp.async.cg.shared.global [%0], [%1], 16;" :: "r"(dst), "l"(src))
#define CPCOMMIT() asm volatile("cp.async.commit_group;" ::: "memory")

__global__ __launch_bounds__(256, 2)
void mma_gemm(const __half* __restrict__ A, const __half* __restrict__ B,
              float* __restrict__ C, int Kp, int Ntot)
{
    __shared__ __align__(16) __half As[2][128 * LDSTR];
    __shared__ __align__(16) __half Bs[2][128 * LDSTR];

    const int tid = threadIdx.x;
    const int lane = tid & 31;
    const int wid = tid >> 5;
    const int warp_m = wid & 3;      // 0..3 -> m offset *32
    const int warp_n = wid >> 2;     // 0..1 -> n offset *64
    const size_t rowA = (size_t)blockIdx.y * 128;
    const size_t rowB = (size_t)blockIdx.x * 128;
    const int nch = Kp >> 5;         // BK = 32

    // cp.async mapping: thread -> one row, two adjacent 16B chunks (32B)
    const int r0  = tid >> 1;            // 0..127
    const int ch0 = (tid & 1) * 2;       // 0 or 2

    const __half* gA = A + (rowA + r0) * Kp + ch0 * 8;
    const __half* gB = B + (rowB + r0) * Kp + ch0 * 8;
    const uint32_t sAr = (uint32_t)__cvta_generic_to_shared(&As[0][r0 * LDSTR + ch0 * 8]);
    const uint32_t sBr = (uint32_t)__cvta_generic_to_shared(&Bs[0][r0 * LDSTR + ch0 * 8]);
    const uint32_t bufstride = 128 * LDSTR * 2;   // bytes between buffers

    float acc[2][8][4];
    #pragma unroll
    for (int i = 0; i < 2; ++i)
        #pragma unroll
        for (int j = 0; j < 8; ++j)
            #pragma unroll
            for (int q = 0; q < 4; ++q) acc[i][j][q] = 0.0f;

    // prologue: load chunks 0 and 1
    #pragma unroll
    for (int t = 0; t < 2; ++t) {
        CPASYNC16(sAr + t * bufstride,      gA + (size_t)t * 32);
        CPASYNC16(sAr + t * bufstride + 16, gA + (size_t)t * 32 + 8);
        CPASYNC16(sBr + t * bufstride,      gB + (size_t)t * 32);
        CPASYNC16(sBr + t * bufstride + 16, gB + (size_t)t * 32 + 8);
        CPCOMMIT();
    }

    // precomputed ldmatrix smem addresses (buffer 0)
    const int arow = warp_m * 32 + (lane & 15);
    const int acol = (lane >> 4) * 8;
    const uint32_t aAddr0 = (uint32_t)__cvta_generic_to_shared(&As[0][arow * LDSTR + acol]);
    const int brow = warp_n * 64 + (lane & 7) + ((lane >> 4) & 1) * 8;
    const int bcol = ((lane >> 3) & 1) * 8;
    const uint32_t bAddr0 = (uint32_t)__cvta_generic_to_shared(&Bs[0][brow * LDSTR + bcol]);

    for (int t = 0; t < nch; ++t) {
        const int buf = t & 1;
        if (t + 1 < nch) asm volatile("cp.async.wait_group 1;" ::: "memory");
        else             asm volatile("cp.async.wait_group 0;" ::: "memory");
        __syncthreads();

        const uint32_t aB = aAddr0 + buf * bufstride;
        const uint32_t bB = bAddr0 + buf * bufstride;
        #pragma unroll
        for (int ks = 0; ks < 2; ++ks) {
            uint32_t af[2][4], bf[4][4];
            #pragma unroll
            for (int im = 0; im < 2; ++im)
                ldsm4(af[im], aB + (im * 16 * LDSTR + ks * 16) * 2);
            #pragma unroll
            for (int ip = 0; ip < 4; ++ip)
                ldsm4(bf[ip], bB + (ip * 16 * LDSTR + ks * 16) * 2);
            #pragma unroll
            for (int im = 0; im < 2; ++im)
                #pragma unroll
                for (int ip = 0; ip < 4; ++ip) {
                    mma16816(acc[im][2 * ip],     af[im], bf[ip][0], bf[ip][1]);
                    mma16816(acc[im][2 * ip + 1], af[im], bf[ip][2], bf[ip][3]);
                }
        }
        __syncthreads();

        if (t + 2 < nch) {
            const size_t go = (size_t)(t + 2) * 32;
            CPASYNC16(sAr + buf * bufstride,      gA + go);
            CPASYNC16(sAr + buf * bufstride + 16, gA + go + 8);
            CPASYNC16(sBr + buf * bufstride,      gB + go);
            CPASYNC16(sBr + buf * bufstride + 16, gB + go + 8);
            CPCOMMIT();
        }
    }

    // epilogue: direct fp32 stores (float2 per fragment half-row)
    const int crow = (int)rowA + warp_m * 32 + (lane >> 2);
    const int ccol = (int)rowB + warp_n * 64 + (lane & 3) * 2;
    #pragma unroll
    for (int im = 0; im < 2; ++im) {
        #pragma unroll
        for (int in = 0; in < 8; ++in) {
            float* p0 = C + (size_t)(crow + im * 16) * Ntot + ccol + in * 8;
            float* p1 = C + (size_t)(crow + im * 16 + 8) * Ntot + ccol + in * 8;
            *(float2*)p0 = make_float2(acc[im][in][0], acc[im][in][1]);
            *(float2*)p1 = make_float2(acc[im][in][2], acc[im][in][3]);
        }
    }
}

// =================== kernel 3: column stats (deterministic) ================
__global__ __launch_bounds__(512)
void colstats_partial(const float* __restrict__ H)
{
    const int c = threadIdx.x;
    const int blk = blockIdx.x;
    float s = 0.0f, q = 0.0f;
    const size_t base = (size_t)blk * 512 * 512;
    #pragma unroll 4
    for (int r = 0; r < 512; ++r) {
        float v = H[base + (size_t)r * 512 + c];
        s += v;
        q += v * v;
    }
    g_part[(size_t)blk * 1024 + c]       = s;
    g_part[(size_t)blk * 1024 + 512 + c] = q;
}

__global__ __launch_bounds__(512)
void colstats_final(int layer)
{
    const int c = threadIdx.x;
    float s = 0.0f, q = 0.0f;
    for (int b = 0; b < 128; ++b) {
        s += g_part[(size_t)b * 1024 + c];
        q += g_part[(size_t)b * 1024 + 512 + c];
    }
    g_stats[(size_t)layer * 1024 + c]       = s;
    g_stats[(size_t)layer * 1024 + 512 + c] = q;
}

// ============ kernel 4a: BN + GELU -> split fp16 into g_A2 =================
__global__ __launch_bounds__(256)
void bn_gelu_split(const float* __restrict__ H,
                   const float* __restrict__ gamma,
                   const float* __restrict__ beta)
{
    const size_t idx = (size_t)blockIdx.x * blockDim.x + threadIdx.x;
    const size_t total = (size_t)MROWS * 512 / 4;
    if (idx >= total) return;
    const int c0 = (int)((idx & 127) * 4);
    const size_t row = idx >> 7;
    const float invM = 1.0f / (float)MROWS;
    const float* st = g_stats;   // layer 0

    float4 v = ((const float4*)H)[idx];
    float o[4] = {v.x, v.y, v.z, v.w};
    #pragma unroll
    for (int j = 0; j < 4; ++j) {
        int c = c0 + j;
        float m   = st[c] * invM;
        float var = st[512 + c] * invM - m * m;
        float inv = rsqrtf(var + BN_EPS);
        float y   = (o[j] - m) * inv * gamma[c] + beta[c];
        o[j] = 0.5f * y * (1.0f + erff(y * 0.70710678118654752f));
    }
    wsplit4(g_A2 + row * K2P, DH, c0, make_float4(o[0], o[1], o[2], o[3]));
}

// ============ kernel 4b: BN + GELU in place (final output) =================
__global__ __launch_bounds__(256)
void bn_gelu_inplace(float* __restrict__ H,
                     const float* __restrict__ gamma,
                     const float* __restrict__ beta)
{
    const size_t idx = (size_t)blockIdx.x * blockDim.x + threadIdx.x;
    const size_t total = (size_t)MROWS * 512 / 4;
    if (idx >= total) return;
    const int c0 = (int)((idx & 127) * 4);
    const float invM = 1.0f / (float)MROWS;
    const float* st = g_stats + 1024;  // layer 1

    float4 v = ((const float4*)H)[idx];
    float o[4] = {v.x, v.y, v.z, v.w};
    #pragma unroll
    for (int j = 0; j < 4; ++j) {
        int c = c0 + j;
        float m   = st[c] * invM;
        float var = st[512 + c] * invM - m * m;
        float inv = rsqrtf(var + BN_EPS);
        float y   = (o[j] - m) * inv * gamma[c] + beta[c];
        o[j] = 0.5f * y * (1.0f + erff(y * 0.70710678118654752f));
    }
    ((float4*)H)[idx] = make_float4(o[0], o[1], o[2], o[3]);
}

// ============================ launcher =====================================
extern "C" void kernel_launch(void* const* d_in, const int* in_sizes, int n_in,
                              void* d_out, int out_size)
{
    const float* sxyz = (const float*)d_in[0];
    const float* spf  = (const float*)d_in[1];
    const float* xyz  = (const float*)d_in[2];
    const float* pf   = (const float*)d_in[3];
    const float* W1   = (const float*)d_in[4];
    const float* g1   = (const float*)d_in[5];
    const float* b1   = (const float*)d_in[6];
    const float* W2   = (const float*)d_in[7];
    const float* g2   = (const float*)d_in[8];
    const float* b2   = (const float*)d_in[9];
    float* out = (float*)d_out;

    __half *pA1, *pA2, *pB1, *pB2;
    float *pH;
    cudaGetSymbolAddress((void**)&pA1, g_A1);
    cudaGetSymbolAddress((void**)&pA2, g_A2);
    cudaGetSymbolAddress((void**)&pB1, g_B1);
    cudaGetSymbolAddress((void**)&pB2, g_B2);
    cudaGetSymbolAddress((void**)&pH,  g_H);

    // 0) weight splits
    wsplit_kernel<<<(DIN * DH + 255) / 256, 256>>>(W1, pB1, DIN, DH);
    wsplit_kernel<<<(DH * DOUT + 255) / 256, 256>>>(W2, pB2, DH, DOUT);

    // 1) 3-NN interpolation + concat + split -> g_A1 [65536, 1152] fp16
    interp_kernel<<<dim3(NPTS / 256, BATCH), 256>>>(sxyz, spf, xyz, pf);

    // 2) GEMM1 (HMMA): g_A1 . g_B1^T -> g_H fp32 [65536, 512]
    mma_gemm<<<dim3(DH / 128, MROWS / 128), 256>>>(pA1, pB1, pH, K1P, DH);

    // 3) BN stats + BN+GELU -> split fp16 g_A2
    colstats_partial<<<128, 512>>>(pH);
    colstats_final<<<1, 512>>>(0);
    bn_gelu_split<<<(MROWS * 512 / 4 + 255) / 256, 256>>>(pH, g1, b1);

    // 4) GEMM2 (HMMA): g_A2 . g_B2^T -> out fp32 [65536, 512]
    mma_gemm<<<dim3(DOUT / 128, MROWS / 128), 256>>>(pA2, pB2, out, K2P, DOUT);

    // 5) BN stats + BN+GELU in place on out
    colstats_partial<<<128, 512>>>(out);
    colstats_final<<<1, 512>>>(1);
    bn_gelu_inplace<<<(MROWS * 512 / 4 + 255) / 256, 256>>>(out, g2, b2);
}

// round 4
// speedup vs baseline: 1.8603x; 1.2126x over previous
#include <cuda_runtime.h>
#include <cuda_fp16.h>
#include <math.h>
#include <stdint.h>

// Problem constants
#define BATCH   8
#define SPTS    2048
#define NPTS    8192
#define FDIM    256
#define CDIM    128
#define DIN     384
#define DH      512
#define DOUT    512
#define MROWS   (BATCH * NPTS)          // 65536
#define EPSF    1.1920929e-07f
#define BN_EPS  1e-5f
#define NOUT    512                     // N for both GEMMs

// ---------------- scratch (device globals) ---------------------------------
__device__ __half g_A1[(size_t)MROWS * 2 * DIN];   // [Ah|Al] of X    100 MB
__device__ __half g_A2[(size_t)MROWS * 2 * DH];    // [Ah|Al] of H'   134 MB
__device__ __half g_B1[(size_t)DH  * 2 * DIN];     // [Bh|Bl] W1^T
__device__ __half g_B2[(size_t)DOUT * 2 * DH];     // [Bh|Bl] W2^T
__device__ float g_H[(size_t)MROWS * DH];          // GEMM1 out       134 MB
__device__ float g_part[512 * 1024];               // per-rowblock col partials
__device__ float g_stats[2 * 512 * 2];

// hi/lo fp16 split write: row[c..c+3]=hi, row[seg+c..]=lo
__device__ __forceinline__ void wsplit4(__half* row, int seg, int c, float4 v) {
    float a[4] = {v.x, v.y, v.z, v.w};
    __half h[4], l[4];
    #pragma unroll
    for (int j = 0; j < 4; ++j) {
        h[j] = __float2half_rn(a[j]);
        l[j] = __float2half_rn(a[j] - __half2float(h[j]));
    }
    __half2* p0 = (__half2*)(row + c);
    __half2* p1 = (__half2*)(row + seg + c);
    p0[0] = __halves2half2(h[0], h[1]); p0[1] = __halves2half2(h[2], h[3]);
    p1[0] = __halves2half2(l[0], l[1]); p1[1] = __halves2half2(l[2], l[3]);
}

// ======================= kernel 1: 3-NN interpolation ======================
__global__ __launch_bounds__(256)
void interp_kernel(const float* __restrict__ sxyz_g,
                   const float* __restrict__ spf,
                   const float* __restrict__ xyz,
                   const float* __restrict__ pf)
{
    __shared__ float sx[SPTS], sy[SPTS], sz[SPTS], sn2[SPTS];
    __shared__ int   s_idx[256][3];
    __shared__ float s_w[256][3];

    const int b   = blockIdx.y;
    const int tid = threadIdx.x;

    const float* sb = sxyz_g + (size_t)b * SPTS * 3;
    for (int j = tid; j < SPTS * 3; j += 256) {
        float v = sb[j];
        int s = j / 3, c = j - 3 * s;
        if      (c == 0) sx[s] = v;
        else if (c == 1) sy[s] = v;
        else             sz[s] = v;
    }
    __syncthreads();
    for (int s = tid; s < SPTS; s += 256)
        sn2[s] = sx[s]*sx[s] + sy[s]*sy[s] + sz[s]*sz[s];
    __syncthreads();

    const int p  = blockIdx.x * 256 + tid;
    const int gp = b * NPTS + p;
    const float px = xyz[(size_t)gp*3 + 0];
    const float py = xyz[(size_t)gp*3 + 1];
    const float pz = xyz[(size_t)gp*3 + 2];
    const float n1 = px*px + py*py + pz*pz;

    float d0 = 3.4e38f, d1 = 3.4e38f, d2 = 3.4e38f;
    int   i0 = 0, i1 = 0, i2 = 0;

    #pragma unroll 4
    for (int s = 0; s < SPTS; ++s) {
        float dot = sx[s]*px + sy[s]*py + sz[s]*pz;
        float d   = -2.0f*dot + n1 + sn2[s];
        if (d < d2) {
            if (d < d1) {
                d2 = d1; i2 = i1;
                if (d < d0) { d1 = d0; i1 = i0; d0 = d; i0 = s; }
                else        { d1 = d;  i1 = s; }
            } else { d2 = d; i2 = s; }
        }
    }

    float w0 = 1.0f / (fmaxf(d0, 0.0f) + EPSF);
    float w1 = 1.0f / (fmaxf(d1, 0.0f) + EPSF);
    float w2 = 1.0f / (fmaxf(d2, 0.0f) + EPSF);
    float inv = 1.0f / (w0 + w1 + w2);
    s_idx[tid][0] = i0; s_idx[tid][1] = i1; s_idx[tid][2] = i2;
    s_w[tid][0] = w0 * inv; s_w[tid][1] = w1 * inv; s_w[tid][2] = w2 * inv;
    __syncthreads();

    const int warp = tid >> 5, lane = tid & 31;
    for (int q = warp; q < 256; q += 8) {
        const int pp   = blockIdx.x * 256 + q;
        const int grow = b * NPTS + pp;
        const float4* r0 = (const float4*)(spf + ((size_t)b*SPTS + s_idx[q][0]) * FDIM);
        const float4* r1 = (const float4*)(spf + ((size_t)b*SPTS + s_idx[q][1]) * FDIM);
        const float4* r2 = (const float4*)(spf + ((size_t)b*SPTS + s_idx[q][2]) * FDIM);
        const float a0 = s_w[q][0], a1 = s_w[q][1], a2 = s_w[q][2];
        __half* arow = g_A1 + (size_t)grow * (2 * DIN);

        const float4 pr4 = ((const float4*)(pf + (size_t)grow * CDIM))[lane];
        wsplit4(arow, DIN, lane * 4, pr4);

        #pragma unroll
        for (int h = 0; h < 2; ++h) {
            int c4 = lane + h * 32;
            float4 va = r0[c4], vb = r1[c4], vc = r2[c4];
            float4 o;
            o.x = a0*va.x + a1*vb.x + a2*vc.x;
            o.y = a0*va.y + a1*vb.y + a2*vc.y;
            o.z = a0*va.z + a1*vb.z + a2*vc.z;
            o.w = a0*va.w + a1*vb.w + a2*vc.w;
            wsplit4(arow, DIN, CDIM + c4 * 4, o);
        }
    }
}

// ============== kernel 1b: split + transpose weights =======================
// W [K, N] row-major -> B'[N, 2K]: [hi | lo]
__global__ __launch_bounds__(256)
void wsplit_kernel(const float* __restrict__ W, __half* __restrict__ Bp,
                   int K, int N)
{
    int i = blockIdx.x * 256 + threadIdx.x;
    if (i >= K * N) return;
    int n = i % N, k = i / N;
    float w = W[(size_t)k * N + n];
    __half h = __float2half_rn(w);
    __half l = __float2half_rn(w - __half2float(h));
    __half* row = Bp + (size_t)n * 2 * K;
    row[k]     = h;
    row[K + k] = l;
}

// ======================= kernel 2: HMMA fp16 GEMM ==========================
// C = Ah.Bh^T + Ah.Bl^T + Al.Bh^T ; A' [M, 2K], B' [N, 2K] K-major fp16.
// CTA 128x128, BK=32, 4-stage cp.async, 8 warps (4x2), warp tile 32x64.
// Fused epilogue: per-CTA column (sum, sumsq) partials -> g_part.
#define LDSTR       40
#define STAGE_BYTES (128 * LDSTR * 2)   // 10240
#define B_SMEM_BASE (4 * STAGE_BYTES)   // 40960
#define GEMM_SMEM   (8 * STAGE_BYTES)   // 81920

__device__ __forceinline__ void ldsm4(uint32_t* r, uint32_t addr) {
    asm volatile("ldmatrix.sync.aligned.m8n8.x4.shared.b16 {%0,%1,%2,%3}, [%4];"
                 : "=r"(r[0]), "=r"(r[1]), "=r"(r[2]), "=r"(r[3]) : "r"(addr));
}
__device__ __forceinline__ void mma16816(float* c, const uint32_t* a,
                                         uint32_t b0, uint32_t b1) {
    asm volatile(
        "mma.sync.aligned.m16n8k16.row.col.f32.f16.f16.f32 "
        "{%0,%1,%2,%3}, {%4,%5,%6,%7}, {%8,%9}, {%0,%1,%2,%3};"
        : "+f"(c[0]), "+f"(c[1]), "+f"(c[2]), "+f"(c[3])
        : "r"(a[0]), "r"(a[1]), "r"(a[2]), "r"(a[3]), "r"(b0), "r"(b1));
}
#define CPASYNC16(dst, src) \
    asm volatile("cp.async.cg.shared.global [%0], [%1], 16;" :: "r"(dst), "l"(src))
#define CPCOMMIT() asm volatile("cp.async.commit_group;" ::: "memory")

__global__ __launch_bounds__(256, 2)
void mma_gemm(const __half* __restrict__ A, const __half* __restrict__ B,
              float* __restrict__ C, float* __restrict__ gpart, int K)
{
    extern __shared__ __align__(16) char dsm[];

    const int tid  = threadIdx.x;
    const int lane = tid & 31;
    const int wid  = tid >> 5;
    const int warp_m = wid & 3;      // rows *32
    const int warp_n = wid >> 2;     // cols *64
    const size_t rowA = (size_t)blockIdx.y * 128;
    const size_t rowB = (size_t)blockIdx.x * 128;
    const int Kc     = K >> 5;       // 32-wide chunks per segment
    const int nsteps = 3 * Kc;
    const int Aw = 2 * K;            // row widths

    // cp.async mapping: thread -> one row, 32B (two 16B chunks)
    const int r0  = tid >> 1;
    const int ch0 = (tid & 1) * 2;
    const __half* gA = A + (rowA + r0) * Aw + ch0 * 8;
    const __half* gB = B + (rowB + r0) * Aw + ch0 * 8;
    const uint32_t sAr = (uint32_t)__cvta_generic_to_shared(dsm) + (uint32_t)(r0 * LDSTR + ch0 * 8) * 2;
    const uint32_t sBr = sAr + B_SMEM_BASE;

    float acc[2][8][4];
    #pragma unroll
    for (int i = 0; i < 2; ++i)
        #pragma unroll
        for (int j = 0; j < 8; ++j)
            #pragma unroll
            for (int q = 0; q < 4; ++q) acc[i][j][q] = 0.0f;

    // step -> (A chunk, B chunk): per j: (Ah,Bh), (Ah,Bl), (Al,Bh)
    auto issue_step = [&](int s) {
        int j = s / 3, term = s - 3 * j;
        int ach = (term == 2) ? (Kc + j) : j;
        int bch = (term == 1) ? (Kc + j) : j;
        uint32_t dA = sAr + (s & 3) * STAGE_BYTES;
        uint32_t dB = sBr + (s & 3) * STAGE_BYTES;
        const __half* pa = gA + ach * 32;
        const __half* pb = gB + bch * 32;
        CPASYNC16(dA, pa);      CPASYNC16(dA + 16, pa + 8);
        CPASYNC16(dB, pb);      CPASYNC16(dB + 16, pb + 8);
    };

    // prologue: 3 stages in flight
    #pragma unroll
    for (int s = 0; s < 3; ++s) { issue_step(s); CPCOMMIT(); }

    // ldmatrix base addresses (stage 0)
    const int arow = warp_m * 32 + (lane & 15);
    const int acol = (lane >> 4) * 8;
    const uint32_t aAddr0 = (uint32_t)__cvta_generic_to_shared(dsm) + (uint32_t)(arow * LDSTR + acol) * 2;
    const int brow = warp_n * 64 + (lane & 7) + ((lane >> 4) & 1) * 8;
    const int bcol = ((lane >> 3) & 1) * 8;
    const uint32_t bAddr0 = (uint32_t)__cvta_generic_to_shared(dsm) + B_SMEM_BASE + (uint32_t)(brow * LDSTR + bcol) * 2;

    for (int t = 0; t < nsteps; ++t) {
        asm volatile("cp.async.wait_group 2;" ::: "memory");
        __syncthreads();

        const int buf = t & 3;
        const uint32_t aB = aAddr0 + buf * STAGE_BYTES;
        const uint32_t bB = bAddr0 + buf * STAGE_BYTES;
        #pragma unroll
        for (int ks = 0; ks < 2; ++ks) {
            uint32_t af[2][4], bf[4][4];
            #pragma unroll
            for (int im = 0; im < 2; ++im)
                ldsm4(af[im], aB + (im * 16 * LDSTR + ks * 16) * 2);
            #pragma unroll
            for (int ip = 0; ip < 4; ++ip)
                ldsm4(bf[ip], bB + (ip * 16 * LDSTR + ks * 16) * 2);
            #pragma unroll
            for (int im = 0; im < 2; ++im)
                #pragma unroll
                for (int ip = 0; ip < 4; ++ip) {
                    mma16816(acc[im][2 * ip],     af[im], bf[ip][0], bf[ip][1]);
                    mma16816(acc[im][2 * ip + 1], af[im], bf[ip][2], bf[ip][3]);
                }
        }

        const int ns = t + 3;
        if (ns < nsteps) issue_step(ns);
        CPCOMMIT();
    }

    // ---- store C (fp32) ----
    const int crow = (int)rowA + warp_m * 32 + (lane >> 2);
    const int ccol = (int)rowB + warp_n * 64 + (lane & 3) * 2;
    #pragma unroll
    for (int im = 0; im < 2; ++im) {
        #pragma unroll
        for (int in = 0; in < 8; ++in) {
            float* p0 = C + (size_t)(crow + im * 16) * NOUT + ccol + in * 8;
            float* p1 = C + (size_t)(crow + im * 16 + 8) * NOUT + ccol + in * 8;
            *(float2*)p0 = make_float2(acc[im][in][0], acc[im][in][1]);
            *(float2*)p1 = make_float2(acc[im][in][2], acc[im][in][3]);
        }
    }

    // ---- fused column stats: per-CTA (sum, sumsq) over 128 rows ----
    // per-thread: 16 columns (in,e), 4 row instances each
    float cs[16], cq[16];
    #pragma unroll
    for (int in = 0; in < 8; ++in) {
        #pragma unroll
        for (int e = 0; e < 2; ++e) {
            float s = 0.0f, q = 0.0f;
            #pragma unroll
            for (int im = 0; im < 2; ++im) {
                float v0 = acc[im][in][e], v1 = acc[im][in][2 + e];
                s += v0 + v1;
                q += v0 * v0 + v1 * v1;
            }
            cs[in * 2 + e] = s;
            cq[in * 2 + e] = q;
        }
    }
    #pragma unroll
    for (int m = 4; m <= 16; m <<= 1) {
        #pragma unroll
        for (int i = 0; i < 16; ++i) {
            cs[i] += __shfl_xor_sync(0xFFFFFFFF, cs[i], m);
            cq[i] += __shfl_xor_sync(0xFFFFFFFF, cq[i], m);
        }
    }

    __syncthreads();               // all smem stage reads done; reuse as sred
    float* sred = (float*)dsm;     // [8 warps][64 cols][2]
    if (lane < 4) {
        #pragma unroll
        for (int i = 0; i < 16; ++i) {
            int cloc = (lane & 3) * 2 + (i & 1) + (i >> 1) * 8;
            sred[(wid * 64 + cloc) * 2 + 0] = cs[i];
            sred[(wid * 64 + cloc) * 2 + 1] = cq[i];
        }
    }
    __syncthreads();

    {
        const int col  = tid & 127;
        const int stat = tid >> 7;
        const int wn = col >> 6, cl = col & 63;
        float v = 0.0f;
        #pragma unroll
        for (int wm = 0; wm < 4; ++wm)
            v += sred[((wn * 4 + wm) * 64 + cl) * 2 + stat];
        gpart[(size_t)blockIdx.y * 1024 + stat * 512 + blockIdx.x * 128 + col] = v;
    }
}

// =================== kernel 3: final column stats ==========================
__global__ __launch_bounds__(512)
void colstats_final(int layer)
{
    const int c = threadIdx.x;
    float s = 0.0f, q = 0.0f;
    for (int b = 0; b < 512; ++b) {
        s += g_part[(size_t)b * 1024 + c];
        q += g_part[(size_t)b * 1024 + 512 + c];
    }
    g_stats[(size_t)layer * 1024 + c]       = s;
    g_stats[(size_t)layer * 1024 + 512 + c] = q;
}

// ============ kernel 4a: BN + GELU -> split fp16 into g_A2 =================
__global__ __launch_bounds__(256)
void bn_gelu_split(const float* __restrict__ H,
                   const float* __restrict__ gamma,
                   const float* __restrict__ beta)
{
    const size_t idx = (size_t)blockIdx.x * blockDim.x + threadIdx.x;
    const size_t total = (size_t)MROWS * 512 / 4;
    if (idx >= total) return;
    const int c0 = (int)((idx & 127) * 4);
    const size_t row = idx >> 7;
    const float invM = 1.0f / (float)MROWS;
    const float* st = g_stats;   // layer 0

    float4 v = ((const float4*)H)[idx];
    float o[4] = {v.x, v.y, v.z, v.w};
    #pragma unroll
    for (int j = 0; j < 4; ++j) {
        int c = c0 + j;
        float m   = st[c] * invM;
        float var = st[512 + c] * invM - m * m;
        float inv = rsqrtf(var + BN_EPS);
        float y   = (o[j] - m) * inv * gamma[c] + beta[c];
        o[j] = 0.5f * y * (1.0f + erff(y * 0.70710678118654752f));
    }
    wsplit4(g_A2 + row * (2 * DH), DH, c0, make_float4(o[0], o[1], o[2], o[3]));
}

// ============ kernel 4b: BN + GELU in place (final output) =================
__global__ __launch_bounds__(256)
void bn_gelu_inplace(float* __restrict__ H,
                     const float* __restrict__ gamma,
                     const float* __restrict__ beta)
{
    const size_t idx = (size_t)blockIdx.x * blockDim.x + threadIdx.x;
    const size_t total = (size_t)MROWS * 512 / 4;
    if (idx >= total) return;
    const int c0 = (int)((idx & 127) * 4);
    const float invM = 1.0f / (float)MROWS;
    const float* st = g_stats + 1024;  // layer 1

    float4 v = ((const float4*)H)[idx];
    float o[4] = {v.x, v.y, v.z, v.w};
    #pragma unroll
    for (int j = 0; j < 4; ++j) {
        int c = c0 + j;
        float m   = st[c] * invM;
        float var = st[512 + c] * invM - m * m;
        float inv = rsqrtf(var + BN_EPS);
        float y   = (o[j] - m) * inv * gamma[c] + beta[c];
        o[j] = 0.5f * y * (1.0f + erff(y * 0.70710678118654752f));
    }
    ((float4*)H)[idx] = make_float4(o[0], o[1], o[2], o[3]);
}

// ============================ launcher =====================================
extern "C" void kernel_launch(void* const* d_in, const int* in_sizes, int n_in,
                              void* d_out, int out_size)
{
    const float* sxyz = (const float*)d_in[0];
    const float* spf  = (const float*)d_in[1];
    const float* xyz  = (const float*)d_in[2];
    const float* pf   = (const float*)d_in[3];
    const float* W1   = (const float*)d_in[4];
    const float* g1   = (const float*)d_in[5];
    const float* b1   = (const float*)d_in[6];
    const float* W2   = (const float*)d_in[7];
    const float* g2   = (const float*)d_in[8];
    const float* b2   = (const float*)d_in[9];
    float* out = (float*)d_out;

    __half *pA1, *pA2, *pB1, *pB2;
    float *pH, *pPart;
    cudaGetSymbolAddress((void**)&pA1, g_A1);
    cudaGetSymbolAddress((void**)&pA2, g_A2);
    cudaGetSymbolAddress((void**)&pB1, g_B1);
    cudaGetSymbolAddress((void**)&pB2, g_B2);
    cudaGetSymbolAddress((void**)&pH,  g_H);
    cudaGetSymbolAddress((void**)&pPart, g_part);

    cudaFuncSetAttribute(mma_gemm, cudaFuncAttributeMaxDynamicSharedMemorySize, GEMM_SMEM);

    // 0) weight splits
    wsplit_kernel<<<(DIN * DH + 255) / 256, 256>>>(W1, pB1, DIN, DH);
    wsplit_kernel<<<(DH * DOUT + 255) / 256, 256>>>(W2, pB2, DH, DOUT);

    // 1) 3-NN interpolation + concat + split -> g_A1 [65536, 768] fp16
    interp_kernel<<<dim3(NPTS / 256, BATCH), 256>>>(sxyz, spf, xyz, pf);

    // 2) GEMM1 (HMMA, fused stats): g_A1 . g_B1^T -> g_H
    mma_gemm<<<dim3(DH / 128, MROWS / 128), 256, GEMM_SMEM>>>(pA1, pB1, pH, pPart, DIN);

    // 3) stats reduce + BN+GELU -> split fp16 g_A2
    colstats_final<<<1, 512>>>(0);
    bn_gelu_split<<<(MROWS * 512 / 4 + 255) / 256, 256>>>(pH, g1, b1);

    // 4) GEMM2 (HMMA, fused stats): g_A2 . g_B2^T -> out
    mma_gemm<<<dim3(DOUT / 128, MROWS / 128), 256, GEMM_SMEM>>>(pA2, pB2, out, pPart, DH);

    // 5) stats reduce + BN+GELU in place on out
    colstats_final<<<1, 512>>>(1);
    bn_gelu_inplace<<<(MROWS * 512 / 4 + 255) / 256, 256>>>(out, g2, b2);
}

// round 5
// speedup vs baseline: 2.5310x; 1.3605x over previous
#include <cuda_runtime.h>
#include <cuda_fp16.h>
#include <math.h>
#include <stdint.h>

// Problem constants
#define BATCH   8
#define SPTS    2048
#define NPTS    8192
#define FDIM    256
#define CDIM    128
#define DIN     384
#define DH      512
#define DOUT    512
#define MROWS   (BATCH * NPTS)          // 65536
#define EPSF    1.1920929e-07f
#define BN_EPS  1e-5f
#define NOUT    512

// ---------------- scratch (device globals) ---------------------------------
__device__ __half g_A1[(size_t)MROWS * 2 * DIN];   // [Ah|Al] of X    100 MB
__device__ __half g_A2[(size_t)MROWS * 2 * DH];    // [Ah|Al] of H'   134 MB
__device__ __half g_B1[(size_t)DH  * 2 * DIN];     // [Bh|Bh] W1^T
__device__ __half g_B2[(size_t)DOUT * 2 * DH];     // [Bh|Bh] W2^T
__device__ float g_H[(size_t)MROWS * DH];          // GEMM1 out       134 MB
__device__ float g_part[512 * 1024];               // per-rowblock col partials
__device__ float g_part2[32 * 1024];               // mid reduction
__device__ float g_stats[2 * 512 * 2];

// hi/lo fp16 split write: row[c..c+3]=hi, row[seg+c..]=lo
__device__ __forceinline__ void wsplit4(__half* row, int seg, int c, float4 v) {
    float a[4] = {v.x, v.y, v.z, v.w};
    __half h[4], l[4];
    #pragma unroll
    for (int j = 0; j < 4; ++j) {
        h[j] = __float2half_rn(a[j]);
        l[j] = __float2half_rn(a[j] - __half2float(h[j]));
    }
    __half2* p0 = (__half2*)(row + c);
    __half2* p1 = (__half2*)(row + seg + c);
    p0[0] = __halves2half2(h[0], h[1]); p0[1] = __halves2half2(h[2], h[3]);
    p1[0] = __halves2half2(l[0], l[1]); p1[1] = __halves2half2(l[2], l[3]);
}

// ======================= kernel 1: 3-NN interpolation ======================
__global__ __launch_bounds__(256)
void interp_kernel(const float* __restrict__ sxyz_g,
                   const float* __restrict__ spf,
                   const float* __restrict__ xyz,
                   const float* __restrict__ pf)
{
    __shared__ float sx[SPTS], sy[SPTS], sz[SPTS], sn2[SPTS];
    __shared__ int   s_idx[256][3];
    __shared__ float s_w[256][3];

    const int b   = blockIdx.y;
    const int tid = threadIdx.x;

    const float* sb = sxyz_g + (size_t)b * SPTS * 3;
    for (int j = tid; j < SPTS * 3; j += 256) {
        float v = sb[j];
        int s = j / 3, c = j - 3 * s;
        if      (c == 0) sx[s] = v;
        else if (c == 1) sy[s] = v;
        else             sz[s] = v;
    }
    __syncthreads();
    for (int s = tid; s < SPTS; s += 256)
        sn2[s] = sx[s]*sx[s] + sy[s]*sy[s] + sz[s]*sz[s];
    __syncthreads();

    const int p  = blockIdx.x * 256 + tid;
    const int gp = b * NPTS + p;
    const float px = xyz[(size_t)gp*3 + 0];
    const float py = xyz[(size_t)gp*3 + 1];
    const float pz = xyz[(size_t)gp*3 + 2];
    const float n1 = px*px + py*py + pz*pz;

    float d0 = 3.4e38f, d1 = 3.4e38f, d2 = 3.4e38f;
    int   i0 = 0, i1 = 0, i2 = 0;

    #pragma unroll 4
    for (int s = 0; s < SPTS; ++s) {
        float dot = sx[s]*px + sy[s]*py + sz[s]*pz;
        float d   = -2.0f*dot + n1 + sn2[s];
        if (d < d2) {
            if (d < d1) {
                d2 = d1; i2 = i1;
                if (d < d0) { d1 = d0; i1 = i0; d0 = d; i0 = s; }
                else        { d1 = d;  i1 = s; }
            } else { d2 = d; i2 = s; }
        }
    }

    float w0 = 1.0f / (fmaxf(d0, 0.0f) + EPSF);
    float w1 = 1.0f / (fmaxf(d1, 0.0f) + EPSF);
    float w2 = 1.0f / (fmaxf(d2, 0.0f) + EPSF);
    float inv = 1.0f / (w0 + w1 + w2);
    s_idx[tid][0] = i0; s_idx[tid][1] = i1; s_idx[tid][2] = i2;
    s_w[tid][0] = w0 * inv; s_w[tid][1] = w1 * inv; s_w[tid][2] = w2 * inv;
    __syncthreads();

    const int warp = tid >> 5, lane = tid & 31;
    for (int q = warp; q < 256; q += 8) {
        const int pp   = blockIdx.x * 256 + q;
        const int grow = b * NPTS + pp;
        const float4* r0 = (const float4*)(spf + ((size_t)b*SPTS + s_idx[q][0]) * FDIM);
        const float4* r1 = (const float4*)(spf + ((size_t)b*SPTS + s_idx[q][1]) * FDIM);
        const float4* r2 = (const float4*)(spf + ((size_t)b*SPTS + s_idx[q][2]) * FDIM);
        const float a0 = s_w[q][0], a1 = s_w[q][1], a2 = s_w[q][2];
        __half* arow = g_A1 + (size_t)grow * (2 * DIN);

        const float4 pr4 = ((const float4*)(pf + (size_t)grow * CDIM))[lane];
        wsplit4(arow, DIN, lane * 4, pr4);

        #pragma unroll
        for (int h = 0; h < 2; ++h) {
            int c4 = lane + h * 32;
            float4 va = r0[c4], vb = r1[c4], vc = r2[c4];
            float4 o;
            o.x = a0*va.x + a1*vb.x + a2*vc.x;
            o.y = a0*va.y + a1*vb.y + a2*vc.y;
            o.z = a0*va.z + a1*vb.z + a2*vc.z;
            o.w = a0*va.w + a1*vb.w + a2*vc.w;
            wsplit4(arow, DIN, CDIM + c4 * 4, o);
        }
    }
}

// ============== kernel 1b: split + transpose weights =======================
// W [K, N] row-major -> B'[N, 2K]: [hi | hi] (duplicated high part)
__global__ __launch_bounds__(256)
void wsplit_kernel(const float* __restrict__ W, __half* __restrict__ Bp,
                   int K, int N)
{
    int i = blockIdx.x * 256 + threadIdx.x;
    if (i >= K * N) return;
    int n = i % N, k = i / N;
    float w = W[(size_t)k * N + n];
    __half h = __float2half_rn(w);
    __half* row = Bp + (size_t)n * 2 * K;
    row[k]     = h;
    row[K + k] = h;
}

// ======================= kernel 2: HMMA fp16 GEMM ==========================
// Plain C[M,N] = A'[M,Kp] . B'[N,Kp]^T, Kp = 2K. A'=[Ah|Al], B'=[Bh|Bh]
// => C = A . Bh^T (exact in A, hi-only in B).
// CTA 128x128, BK=32, 4-stage cp.async, 8 warps (4x2), warp tile 32x64.
// Fragment prefetch: ks1 ldmatrix issued before ks0 MMAs.
// Fused epilogue: per-CTA column (sum, sumsq) partials -> g_part.
#define LDSTR       40
#define STAGE_BYTES (128 * LDSTR * 2)   // 10240
#define B_SMEM_BASE (4 * STAGE_BYTES)   // 40960
#define GEMM_SMEM   (8 * STAGE_BYTES)   // 81920

__device__ __forceinline__ void ldsm4(uint32_t* r, uint32_t addr) {
    asm volatile("ldmatrix.sync.aligned.m8n8.x4.shared.b16 {%0,%1,%2,%3}, [%4];"
                 : "=r"(r[0]), "=r"(r[1]), "=r"(r[2]), "=r"(r[3]) : "r"(addr));
}
__device__ __forceinline__ void mma16816(float* c, const uint32_t* a,
                                         uint32_t b0, uint32_t b1) {
    asm volatile(
        "mma.sync.aligned.m16n8k16.row.col.f32.f16.f16.f32 "
        "{%0,%1,%2,%3}, {%4,%5,%6,%7}, {%8,%9}, {%0,%1,%2,%3};"
        : "+f"(c[0]), "+f"(c[1]), "+f"(c[2]), "+f"(c[3])
        : "r"(a[0]), "r"(a[1]), "r"(a[2]), "r"(a[3]), "r"(b0), "r"(b1));
}
#define CPASYNC16(dst, src) \
    asm volatile("cp.async.cg.shared.global [%0], [%1], 16;" :: "r"(dst), "l"(src))
#define CPCOMMIT() asm volatile("cp.async.commit_group;" ::: "memory")

__global__ __launch_bounds__(256, 2)
void mma_gemm(const __half* __restrict__ A, const __half* __restrict__ B,
              float* __restrict__ C, float* __restrict__ gpart, int Kp)
{
    extern __shared__ __align__(16) char dsm[];

    const int tid  = threadIdx.x;
    const int lane = tid & 31;
    const int wid  = tid >> 5;
    const int warp_m = wid & 3;      // rows *32
    const int warp_n = wid >> 2;     // cols *64
    const size_t rowA = (size_t)blockIdx.y * 128;
    const size_t rowB = (size_t)blockIdx.x * 128;
    const int nch = Kp >> 5;

    // cp.async mapping: thread -> one row, 32B (two 16B chunks)
    const int r0  = tid >> 1;
    const int ch0 = (tid & 1) * 2;
    const __half* gA = A + (rowA + r0) * Kp + ch0 * 8;
    const __half* gB = B + (rowB + r0) * Kp + ch0 * 8;
    const uint32_t sAr = (uint32_t)__cvta_generic_to_shared(dsm) + (uint32_t)(r0 * LDSTR + ch0 * 8) * 2;
    const uint32_t sBr = sAr + B_SMEM_BASE;

    float acc[2][8][4];
    #pragma unroll
    for (int i = 0; i < 2; ++i)
        #pragma unroll
        for (int j = 0; j < 8; ++j)
            #pragma unroll
            for (int q = 0; q < 4; ++q) acc[i][j][q] = 0.0f;

    auto issue_step = [&](int s) {
        uint32_t dA = sAr + (s & 3) * STAGE_BYTES;
        uint32_t dB = sBr + (s & 3) * STAGE_BYTES;
        const __half* pa = gA + s * 32;
        const __half* pb = gB + s * 32;
        CPASYNC16(dA, pa);      CPASYNC16(dA + 16, pa + 8);
        CPASYNC16(dB, pb);      CPASYNC16(dB + 16, pb + 8);
    };

    #pragma unroll
    for (int s = 0; s < 3; ++s) { issue_step(s); CPCOMMIT(); }

    // ldmatrix base addresses (stage 0)
    const int arow = warp_m * 32 + (lane & 15);
    const int acol = (lane >> 4) * 8;
    const uint32_t aAddr0 = (uint32_t)__cvta_generic_to_shared(dsm) + (uint32_t)(arow * LDSTR + acol) * 2;
    const int brow = warp_n * 64 + (lane & 7) + ((lane >> 4) & 1) * 8;
    const int bcol = ((lane >> 3) & 1) * 8;
    const uint32_t bAddr0 = (uint32_t)__cvta_generic_to_shared(dsm) + B_SMEM_BASE + (uint32_t)(brow * LDSTR + bcol) * 2;

    for (int t = 0; t < nch; ++t) {
        asm volatile("cp.async.wait_group 2;" ::: "memory");
        __syncthreads();

        const int buf = t & 3;
        const uint32_t aB = aAddr0 + buf * STAGE_BYTES;
        const uint32_t bB = bAddr0 + buf * STAGE_BYTES;

        uint32_t af0[2][4], bf0[4][4], af1[2][4], bf1[4][4];
        // ks = 0 fragments
        #pragma unroll
        for (int im = 0; im < 2; ++im) ldsm4(af0[im], aB + (im * 16 * LDSTR) * 2);
        #pragma unroll
        for (int ip = 0; ip < 4; ++ip) ldsm4(bf0[ip], bB + (ip * 16 * LDSTR) * 2);
        // next stage loads go out while ks0 frags settle
        if (t + 3 < nch) issue_step(t + 3);
        CPCOMMIT();
        // ks = 1 fragments (overlap with ks0 MMAs below)
        #pragma unroll
        for (int im = 0; im < 2; ++im) ldsm4(af1[im], aB + (im * 16 * LDSTR + 16) * 2);
        #pragma unroll
        for (int ip = 0; ip < 4; ++ip) ldsm4(bf1[ip], bB + (ip * 16 * LDSTR + 16) * 2);

        #pragma unroll
        for (int im = 0; im < 2; ++im)
            #pragma unroll
            for (int ip = 0; ip < 4; ++ip) {
                mma16816(acc[im][2 * ip],     af0[im], bf0[ip][0], bf0[ip][1]);
                mma16816(acc[im][2 * ip + 1], af0[im], bf0[ip][2], bf0[ip][3]);
            }
        #pragma unroll
        for (int im = 0; im < 2; ++im)
            #pragma unroll
            for (int ip = 0; ip < 4; ++ip) {
                mma16816(acc[im][2 * ip],     af1[im], bf1[ip][0], bf1[ip][1]);
                mma16816(acc[im][2 * ip + 1], af1[im], bf1[ip][2], bf1[ip][3]);
            }
    }

    // ---- store C (fp32) ----
    const int crow = (int)rowA + warp_m * 32 + (lane >> 2);
    const int ccol = (int)rowB + warp_n * 64 + (lane & 3) * 2;
    #pragma unroll
    for (int im = 0; im < 2; ++im) {
        #pragma unroll
        for (int in = 0; in < 8; ++in) {
            float* p0 = C + (size_t)(crow + im * 16) * NOUT + ccol + in * 8;
            float* p1 = C + (size_t)(crow + im * 16 + 8) * NOUT + ccol + in * 8;
            *(float2*)p0 = make_float2(acc[im][in][0], acc[im][in][1]);
            *(float2*)p1 = make_float2(acc[im][in][2], acc[im][in][3]);
        }
    }

    // ---- fused column stats ----
    float cs[16], cq[16];
    #pragma unroll
    for (int in = 0; in < 8; ++in) {
        #pragma unroll
        for (int e = 0; e < 2; ++e) {
            float s = 0.0f, q = 0.0f;
            #pragma unroll
            for (int im = 0; im < 2; ++im) {
                float v0 = acc[im][in][e], v1 = acc[im][in][2 + e];
                s += v0 + v1;
                q += v0 * v0 + v1 * v1;
            }
            cs[in * 2 + e] = s;
            cq[in * 2 + e] = q;
        }
    }
    #pragma unroll
    for (int m = 4; m <= 16; m <<= 1) {
        #pragma unroll
        for (int i = 0; i < 16; ++i) {
            cs[i] += __shfl_xor_sync(0xFFFFFFFF, cs[i], m);
            cq[i] += __shfl_xor_sync(0xFFFFFFFF, cq[i], m);
        }
    }

    asm volatile("cp.async.wait_group 0;" ::: "memory");
    __syncthreads();
    float* sred = (float*)dsm;     // [8 warps][64 cols][2]
    if (lane < 4) {
        #pragma unroll
        for (int i = 0; i < 16; ++i) {
            int cloc = (lane & 3) * 2 + (i & 1) + (i >> 1) * 8;
            sred[(wid * 64 + cloc) * 2 + 0] = cs[i];
            sred[(wid * 64 + cloc) * 2 + 1] = cq[i];
        }
    }
    __syncthreads();

    {
        const int col  = tid & 127;
        const int stat = tid >> 7;
        const int wn = col >> 6, cl = col & 63;
        float v = 0.0f;
        #pragma unroll
        for (int wm = 0; wm < 4; ++wm)
            v += sred[((wn * 4 + wm) * 64 + cl) * 2 + stat];
        gpart[(size_t)blockIdx.y * 1024 + stat * 512 + blockIdx.x * 128 + col] = v;
    }
}

// =================== kernel 3: hierarchical column stats ===================
__global__ __launch_bounds__(512)
void colstats_mid()
{
    const int c = threadIdx.x;
    const int blk = blockIdx.x;        // 0..31, 16 rowblocks each
    float s = 0.0f, q = 0.0f;
    #pragma unroll 4
    for (int b = 0; b < 16; ++b) {
        s += g_part[(size_t)(blk * 16 + b) * 1024 + c];
        q += g_part[(size_t)(blk * 16 + b) * 1024 + 512 + c];
    }
    g_part2[(size_t)blk * 1024 + c]       = s;
    g_part2[(size_t)blk * 1024 + 512 + c] = q;
}

__global__ __launch_bounds__(512)
void colstats_final(int layer)
{
    const int c = threadIdx.x;
    float s = 0.0f, q = 0.0f;
    #pragma unroll
    for (int b = 0; b < 32; ++b) {
        s += g_part2[(size_t)b * 1024 + c];
        q += g_part2[(size_t)b * 1024 + 512 + c];
    }
    g_stats[(size_t)layer * 1024 + c]       = s;
    g_stats[(size_t)layer * 1024 + 512 + c] = q;
}

// ============ kernel 4a: BN + GELU -> split fp16 into g_A2 =================
__global__ __launch_bounds__(256)
void bn_gelu_split(const float* __restrict__ H,
                   const float* __restrict__ gamma,
                   const float* __restrict__ beta)
{
    const size_t idx = (size_t)blockIdx.x * blockDim.x + threadIdx.x;
    const size_t total = (size_t)MROWS * 512 / 4;
    if (idx >= total) return;
    const int c0 = (int)((idx & 127) * 4);
    const size_t row = idx >> 7;
    const float invM = 1.0f / (float)MROWS;
    const float* st = g_stats;   // layer 0

    float4 v = ((const float4*)H)[idx];
    float o[4] = {v.x, v.y, v.z, v.w};
    #pragma unroll
    for (int j = 0; j < 4; ++j) {
        int c = c0 + j;
        float m   = st[c] * invM;
        float var = st[512 + c] * invM - m * m;
        float inv = rsqrtf(var + BN_EPS);
        float y   = (o[j] - m) * inv * gamma[c] + beta[c];
        o[j] = 0.5f * y * (1.0f + erff(y * 0.70710678118654752f));
    }
    wsplit4(g_A2 + row * (2 * DH), DH, c0, make_float4(o[0], o[1], o[2], o[3]));
}

// ============ kernel 4b: BN + GELU in place (final output) =================
__global__ __launch_bounds__(256)
void bn_gelu_inplace(float* __restrict__ H,
                     const float* __restrict__ gamma,
                     const float* __restrict__ beta)
{
    const size_t idx = (size_t)blockIdx.x * blockDim.x + threadIdx.x;
    const size_t total = (size_t)MROWS * 512 / 4;
    if (idx >= total) return;
    const int c0 = (int)((idx & 127) * 4);
    const float invM = 1.0f / (float)MROWS;
    const float* st = g_stats + 1024;  // layer 1

    float4 v = ((const float4*)H)[idx];
    float o[4] = {v.x, v.y, v.z, v.w};
    #pragma unroll
    for (int j = 0; j < 4; ++j) {
        int c = c0 + j;
        float m   = st[c] * invM;
        float var = st[512 + c] * invM - m * m;
        float inv = rsqrtf(var + BN_EPS);
        float y   = (o[j] - m) * inv * gamma[c] + beta[c];
        o[j] = 0.5f * y * (1.0f + erff(y * 0.70710678118654752f));
    }
    ((float4*)H)[idx] = make_float4(o[0], o[1], o[2], o[3]);
}

// ============================ launcher =====================================
extern "C" void kernel_launch(void* const* d_in, const int* in_sizes, int n_in,
                              void* d_out, int out_size)
{
    const float* sxyz = (const float*)d_in[0];
    const float* spf  = (const float*)d_in[1];
    const float* xyz  = (const float*)d_in[2];
    const float* pf   = (const float*)d_in[3];
    const float* W1   = (const float*)d_in[4];
    const float* g1   = (const float*)d_in[5];
    const float* b1   = (const float*)d_in[6];
    const float* W2   = (const float*)d_in[7];
    const float* g2   = (const float*)d_in[8];
    const float* b2   = (const float*)d_in[9];
    float* out = (float*)d_out;

    __half *pA1, *pA2, *pB1, *pB2;
    float *pH, *pPart;
    cudaGetSymbolAddress((void**)&pA1, g_A1);
    cudaGetSymbolAddress((void**)&pA2, g_A2);
    cudaGetSymbolAddress((void**)&pB1, g_B1);
    cudaGetSymbolAddress((void**)&pB2, g_B2);
    cudaGetSymbolAddress((void**)&pH,  g_H);
    cudaGetSymbolAddress((void**)&pPart, g_part);

    cudaFuncSetAttribute(mma_gemm, cudaFuncAttributeMaxDynamicSharedMemorySize, GEMM_SMEM);

    // 0) weight splits (hi duplicated)
    wsplit_kernel<<<(DIN * DH + 255) / 256, 256>>>(W1, pB1, DIN, DH);
    wsplit_kernel<<<(DH * DOUT + 255) / 256, 256>>>(W2, pB2, DH, DOUT);

    // 1) 3-NN interpolation + concat + split -> g_A1 [65536, 768] fp16
    interp_kernel<<<dim3(NPTS / 256, BATCH), 256>>>(sxyz, spf, xyz, pf);

    // 2) GEMM1 (HMMA, fused stats): Kp = 768
    mma_gemm<<<dim3(DH / 128, MROWS / 128), 256, GEMM_SMEM>>>(pA1, pB1, pH, pPart, 2 * DIN);

    // 3) stats reduce + BN+GELU -> split fp16 g_A2
    colstats_mid<<<32, 512>>>();
    colstats_final<<<1, 512>>>(0);
    bn_gelu_split<<<(MROWS * 512 / 4 + 255) / 256, 256>>>(pH, g1, b1);

    // 4) GEMM2 (HMMA, fused stats): Kp = 1024
    mma_gemm<<<dim3(DOUT / 128, MROWS / 128), 256, GEMM_SMEM>>>(pA2, pB2, out, pPart, 2 * DH);

    // 5) stats reduce + BN+GELU in place on out
    colstats_mid<<<32, 512>>>();
    colstats_final<<<1, 512>>>(1);
    bn_gelu_inplace<<<(MROWS * 512 / 4 + 255) / 256, 256>>>(out, g2, b2);
}

// round 6
// speedup vs baseline: 3.0387x; 1.2006x over previous
#include <cuda_runtime.h>
#include <cuda_fp16.h>
#include <math.h>
#include <stdint.h>

// Problem constants
#define BATCH   8
#define SPTS    2048
#define NPTS    8192
#define FDIM    256
#define CDIM    128
#define DIN     384
#define DH      512
#define DOUT    512
#define MROWS   (BATCH * NPTS)          // 65536
#define EPSF    1.1920929e-07f
#define BN_EPS  1e-5f
#define NOUT    512

// ---------------- scratch (device globals) ---------------------------------
__device__ __half g_A1[(size_t)MROWS * 2 * DIN];   // [Ah|Al] of X    100 MB
__device__ __half g_A2[(size_t)MROWS * 2 * DH];    // [Ah|Al] of H'   134 MB
__device__ __half g_B1[(size_t)DH  * DIN];         // Bh W1^T
__device__ __half g_B2[(size_t)DOUT * DH];         // Bh W2^T
__device__ float g_H[(size_t)MROWS * DH];          // GEMM1 out       134 MB
__device__ float g_part[512 * 1024];               // per-rowblock col partials
__device__ float g_part2[32 * 1024];               // mid reduction
__device__ float g_stats[2 * 512 * 2];             // [layer][a(512)|b(512)]

// hi/lo fp16 split write: row[c..c+3]=hi, row[seg+c..]=lo
__device__ __forceinline__ void wsplit4(__half* row, int seg, int c, float4 v) {
    float a[4] = {v.x, v.y, v.z, v.w};
    __half h[4], l[4];
    #pragma unroll
    for (int j = 0; j < 4; ++j) {
        h[j] = __float2half_rn(a[j]);
        l[j] = __float2half_rn(a[j] - __half2float(h[j]));
    }
    __half2* p0 = (__half2*)(row + c);
    __half2* p1 = (__half2*)(row + seg + c);
    p0[0] = __halves2half2(h[0], h[1]); p0[1] = __halves2half2(h[2], h[3]);
    p1[0] = __halves2half2(l[0], l[1]); p1[1] = __halves2half2(l[2], l[3]);
}

// fast exact-GELU: A&S 7.1.26 erf (abs err ~1.5e-7)
__device__ __forceinline__ float gelu_f(float y) {
    float u = 0.70710678118654752f * y;
    float a = fabsf(u);
    float t = __frcp_rn(fmaf(0.3275911f, a, 1.0f));
    float p = fmaf(1.061405429f, t, -1.453152027f);
    p = fmaf(p, t, 1.421413741f);
    p = fmaf(p, t, -0.284496736f);
    p = fmaf(p, t, 0.254829592f);
    p = p * t;
    float e = __expf(-u * u);
    float erfv = fmaf(-p, e, 1.0f);
    erfv = copysignf(erfv, u);
    return 0.5f * y * (1.0f + erfv);
}

// ======================= kernel 1: 3-NN interpolation ======================
__global__ __launch_bounds__(256)
void interp_kernel(const float* __restrict__ sxyz_g,
                   const float* __restrict__ spf,
                   const float* __restrict__ xyz,
                   const float* __restrict__ pf)
{
    __shared__ float4 s4[SPTS];
    __shared__ int   s_idx[256][3];
    __shared__ float s_w[256][3];

    const int b   = blockIdx.y;
    const int tid = threadIdx.x;

    const float* sb = sxyz_g + (size_t)b * SPTS * 3;
    for (int j = tid; j < SPTS; j += 256) {
        float x = sb[3 * j], y = sb[3 * j + 1], z = sb[3 * j + 2];
        s4[j] = make_float4(x, y, z, x * x + y * y + z * z);
    }
    __syncthreads();

    const int p  = blockIdx.x * 256 + tid;
    const int gp = b * NPTS + p;
    const float px = xyz[(size_t)gp*3 + 0];
    const float py = xyz[(size_t)gp*3 + 1];
    const float pz = xyz[(size_t)gp*3 + 2];
    const float n1 = px*px + py*py + pz*pz;

    float d0 = 3.4e38f, d1 = 3.4e38f, d2 = 3.4e38f;
    int   i0 = 0, i1 = 0, i2 = 0;

    #pragma unroll 4
    for (int s = 0; s < SPTS; ++s) {
        float4 v = s4[s];
        float dot = v.x*px + v.y*py + v.z*pz;
        float d   = fmaf(-2.0f, dot, n1 + v.w);
        if (d < d2) {
            if (d < d1) {
                d2 = d1; i2 = i1;
                if (d < d0) { d1 = d0; i1 = i0; d0 = d; i0 = s; }
                else        { d1 = d;  i1 = s; }
            } else { d2 = d; i2 = s; }
        }
    }

    float w0 = 1.0f / (fmaxf(d0, 0.0f) + EPSF);
    float w1 = 1.0f / (fmaxf(d1, 0.0f) + EPSF);
    float w2 = 1.0f / (fmaxf(d2, 0.0f) + EPSF);
    float inv = 1.0f / (w0 + w1 + w2);
    s_idx[tid][0] = i0; s_idx[tid][1] = i1; s_idx[tid][2] = i2;
    s_w[tid][0] = w0 * inv; s_w[tid][1] = w1 * inv; s_w[tid][2] = w2 * inv;
    __syncthreads();

    const int warp = tid >> 5, lane = tid & 31;
    for (int q = warp; q < 256; q += 8) {
        const int pp   = blockIdx.x * 256 + q;
        const int grow = b * NPTS + pp;
        const float4* r0 = (const float4*)(spf + ((size_t)b*SPTS + s_idx[q][0]) * FDIM);
        const float4* r1 = (const float4*)(spf + ((size_t)b*SPTS + s_idx[q][1]) * FDIM);
        const float4* r2 = (const float4*)(spf + ((size_t)b*SPTS + s_idx[q][2]) * FDIM);
        const float a0 = s_w[q][0], a1 = s_w[q][1], a2 = s_w[q][2];
        __half* arow = g_A1 + (size_t)grow * (2 * DIN);

        const float4 pr4 = ((const float4*)(pf + (size_t)grow * CDIM))[lane];
        wsplit4(arow, DIN, lane * 4, pr4);

        #pragma unroll
        for (int h = 0; h < 2; ++h) {
            int c4 = lane + h * 32;
            float4 va = r0[c4], vb = r1[c4], vc = r2[c4];
            float4 o;
            o.x = a0*va.x + a1*vb.x + a2*vc.x;
            o.y = a0*va.y + a1*vb.y + a2*vc.y;
            o.z = a0*va.z + a1*vb.z + a2*vc.z;
            o.w = a0*va.w + a1*vb.w + a2*vc.w;
            wsplit4(arow, DIN, CDIM + c4 * 4, o);
        }
    }
}

// ============== kernel 1b: transpose + hi-cast weights =====================
// W [K, N] row-major -> B[N, K] = hi(W^T)
__global__ __launch_bounds__(256)
void wsplit_kernel(const float* __restrict__ W, __half* __restrict__ Bp,
                   int K, int N)
{
    int i = blockIdx.x * 256 + threadIdx.x;
    if (i >= K * N) return;
    int n = i % N, k = i / N;
    float w = W[(size_t)k * N + n];
    Bp[(size_t)n * K + k] = __float2half_rn(w);
}

// ======================= kernel 2: HMMA fp16 GEMM ==========================
// C[M,N] = (Ah + Al) . Bh^T.  A' [M, 2K] = [Ah|Al], B [N, K] hi only.
// CTA 128x128, real-K chunk 32, 3-stage cp.async ring (Ah,Al,B per stage),
// B tile loaded once per chunk, reused by hi and lo MMAs.
// Fused epilogue: per-CTA column (sum, sumsq) partials -> g_part.
#define LDSTR       40
#define TILE_BYTES  (128 * LDSTR * 2)   // 10240
#define STG         (3 * TILE_BYTES)    // 30720 per stage (Ah|Al|B)
#define GEMM_SMEM   (3 * STG)           // 92160

__device__ __forceinline__ void ldsm4(uint32_t* r, uint32_t addr) {
    asm volatile("ldmatrix.sync.aligned.m8n8.x4.shared.b16 {%0,%1,%2,%3}, [%4];"
                 : "=r"(r[0]), "=r"(r[1]), "=r"(r[2]), "=r"(r[3]) : "r"(addr));
}
__device__ __forceinline__ void mma16816(float* c, const uint32_t* a,
                                         uint32_t b0, uint32_t b1) {
    asm volatile(
        "mma.sync.aligned.m16n8k16.row.col.f32.f16.f16.f32 "
        "{%0,%1,%2,%3}, {%4,%5,%6,%7}, {%8,%9}, {%0,%1,%2,%3};"
        : "+f"(c[0]), "+f"(c[1]), "+f"(c[2]), "+f"(c[3])
        : "r"(a[0]), "r"(a[1]), "r"(a[2]), "r"(a[3]), "r"(b0), "r"(b1));
}
#define CPASYNC16(dst, src) \
    asm volatile("cp.async.cg.shared.global [%0], [%1], 16;" :: "r"(dst), "l"(src))
#define CPCOMMIT() asm volatile("cp.async.commit_group;" ::: "memory")

__global__ __launch_bounds__(256, 2)
void mma_gemm(const __half* __restrict__ A, const __half* __restrict__ B,
              float* __restrict__ C, float* __restrict__ gpart, int K)
{
    extern __shared__ __align__(16) char dsm[];

    const int tid  = threadIdx.x;
    const int lane = tid & 31;
    const int wid  = tid >> 5;
    const int warp_m = wid & 3;      // rows *32
    const int warp_n = wid >> 2;     // cols *64
    const size_t rowA = (size_t)blockIdx.y * 128;
    const size_t rowB = (size_t)blockIdx.x * 128;
    const int nch = K >> 5;
    const int Aw  = 2 * K;

    // cp.async mapping: thread -> one row, 32B (two 16B chunks) per tile
    const int r0  = tid >> 1;
    const int ch0 = (tid & 1) * 2;
    const __half* gAh = A + (rowA + r0) * Aw + ch0 * 8;
    const __half* gAl = gAh + K;
    const __half* gB  = B + (rowB + r0) * K + ch0 * 8;
    const uint32_t sbase = (uint32_t)__cvta_generic_to_shared(dsm);
    const uint32_t sRow  = sbase + (uint32_t)(r0 * LDSTR + ch0 * 8) * 2;

    float acc[2][8][4];
    #pragma unroll
    for (int i = 0; i < 2; ++i)
        #pragma unroll
        for (int j = 0; j < 8; ++j)
            #pragma unroll
            for (int q = 0; q < 4; ++q) acc[i][j][q] = 0.0f;

    auto issue_step = [&](int s, int slot) {
        uint32_t off = (uint32_t)slot * STG;
        const __half* ph = gAh + s * 32;
        const __half* pl = gAl + s * 32;
        const __half* pb = gB  + s * 32;
        CPASYNC16(sRow + off,                    ph);
        CPASYNC16(sRow + off + 16,               ph + 8);
        CPASYNC16(sRow + off + TILE_BYTES,       pl);
        CPASYNC16(sRow + off + TILE_BYTES + 16,  pl + 8);
        CPASYNC16(sRow + off + 2 * TILE_BYTES,      pb);
        CPASYNC16(sRow + off + 2 * TILE_BYTES + 16, pb + 8);
    };

    issue_step(0, 0); CPCOMMIT();
    issue_step(1, 1); CPCOMMIT();

    // ldmatrix base addresses (stage slot 0)
    const int arow = warp_m * 32 + (lane & 15);
    const int acol = (lane >> 4) * 8;
    const uint32_t aAddr0 = sbase + (uint32_t)(arow * LDSTR + acol) * 2;
    const int brow = warp_n * 64 + (lane & 7) + ((lane >> 4) & 1) * 8;
    const int bcol = ((lane >> 3) & 1) * 8;
    const uint32_t bAddr0 = sbase + 2 * TILE_BYTES + (uint32_t)(brow * LDSTR + bcol) * 2;

    int cslot = 0, islot = 2;
    for (int t = 0; t < nch; ++t) {
        asm volatile("cp.async.wait_group 1;" ::: "memory");
        __syncthreads();

        const uint32_t aB = aAddr0 + cslot * STG;          // Ah tile
        const uint32_t lB = aB + TILE_BYTES;               // Al tile
        const uint32_t bB = bAddr0 + cslot * STG;          // B tile

        #pragma unroll
        for (int ks = 0; ks < 2; ++ks) {
            uint32_t ah[2][4], al[2][4], bf[4][4];
            #pragma unroll
            for (int im = 0; im < 2; ++im) ldsm4(ah[im], aB + (im * 16 * LDSTR + ks * 16) * 2);
            #pragma unroll
            for (int im = 0; im < 2; ++im) ldsm4(al[im], lB + (im * 16 * LDSTR + ks * 16) * 2);
            #pragma unroll
            for (int ip = 0; ip < 4; ++ip) ldsm4(bf[ip], bB + (ip * 16 * LDSTR + ks * 16) * 2);

            if (ks == 0) {
                if (t + 2 < nch) issue_step(t + 2, islot);
                CPCOMMIT();
            }

            #pragma unroll
            for (int im = 0; im < 2; ++im)
                #pragma unroll
                for (int ip = 0; ip < 4; ++ip) {
                    mma16816(acc[im][2 * ip],     ah[im], bf[ip][0], bf[ip][1]);
                    mma16816(acc[im][2 * ip + 1], ah[im], bf[ip][2], bf[ip][3]);
                }
            #pragma unroll
            for (int im = 0; im < 2; ++im)
                #pragma unroll
                for (int ip = 0; ip < 4; ++ip) {
                    mma16816(acc[im][2 * ip],     al[im], bf[ip][0], bf[ip][1]);
                    mma16816(acc[im][2 * ip + 1], al[im], bf[ip][2], bf[ip][3]);
                }
        }

        cslot = (cslot == 2) ? 0 : cslot + 1;
        islot = (islot == 2) ? 0 : islot + 1;
    }

    // ---- store C (fp32) ----
    const int crow = (int)rowA + warp_m * 32 + (lane >> 2);
    const int ccol = (int)rowB + warp_n * 64 + (lane & 3) * 2;
    #pragma unroll
    for (int im = 0; im < 2; ++im) {
        #pragma unroll
        for (int in = 0; in < 8; ++in) {
            float* p0 = C + (size_t)(crow + im * 16) * NOUT + ccol + in * 8;
            float* p1 = C + (size_t)(crow + im * 16 + 8) * NOUT + ccol + in * 8;
            *(float2*)p0 = make_float2(acc[im][in][0], acc[im][in][1]);
            *(float2*)p1 = make_float2(acc[im][in][2], acc[im][in][3]);
        }
    }

    // ---- fused column stats ----
    float cs[16], cq[16];
    #pragma unroll
    for (int in = 0; in < 8; ++in) {
        #pragma unroll
        for (int e = 0; e < 2; ++e) {
            float s = 0.0f, q = 0.0f;
            #pragma unroll
            for (int im = 0; im < 2; ++im) {
                float v0 = acc[im][in][e], v1 = acc[im][in][2 + e];
                s += v0 + v1;
                q += v0 * v0 + v1 * v1;
            }
            cs[in * 2 + e] = s;
            cq[in * 2 + e] = q;
        }
    }
    #pragma unroll
    for (int m = 4; m <= 16; m <<= 1) {
        #pragma unroll
        for (int i = 0; i < 16; ++i) {
            cs[i] += __shfl_xor_sync(0xFFFFFFFF, cs[i], m);
            cq[i] += __shfl_xor_sync(0xFFFFFFFF, cq[i], m);
        }
    }

    asm volatile("cp.async.wait_group 0;" ::: "memory");
    __syncthreads();
    float* sred = (float*)dsm;     // [8 warps][64 cols][2]
    if (lane < 4) {
        #pragma unroll
        for (int i = 0; i < 16; ++i) {
            int cloc = (lane & 3) * 2 + (i & 1) + (i >> 1) * 8;
            sred[(wid * 64 + cloc) * 2 + 0] = cs[i];
            sred[(wid * 64 + cloc) * 2 + 1] = cq[i];
        }
    }
    __syncthreads();

    {
        const int col  = tid & 127;
        const int stat = tid >> 7;
        const int wn = col >> 6, cl = col & 63;
        float v = 0.0f;
        #pragma unroll
        for (int wm = 0; wm < 4; ++wm)
            v += sred[((wn * 4 + wm) * 64 + cl) * 2 + stat];
        gpart[(size_t)blockIdx.y * 1024 + stat * 512 + blockIdx.x * 128 + col] = v;
    }
}

// =================== kernel 3: hierarchical column stats ===================
__global__ __launch_bounds__(512)
void colstats_mid()
{
    const int c = threadIdx.x;
    const int blk = blockIdx.x;        // 0..31, 16 rowblocks each
    float s = 0.0f, q = 0.0f;
    #pragma unroll 4
    for (int b = 0; b < 16; ++b) {
        s += g_part[(size_t)(blk * 16 + b) * 1024 + c];
        q += g_part[(size_t)(blk * 16 + b) * 1024 + 512 + c];
    }
    g_part2[(size_t)blk * 1024 + c]       = s;
    g_part2[(size_t)blk * 1024 + 512 + c] = q;
}

// final reduce + fold BN into scale/shift: a = gamma*rsqrt(var+eps), b = beta - m*a
__global__ __launch_bounds__(512)
void colstats_final(const float* __restrict__ gamma,
                    const float* __restrict__ beta, int layer)
{
    const int c = threadIdx.x;
    float s = 0.0f, q = 0.0f;
    #pragma unroll
    for (int b = 0; b < 32; ++b) {
        s += g_part2[(size_t)b * 1024 + c];
        q += g_part2[(size_t)b * 1024 + 512 + c];
    }
    const float invM = 1.0f / (float)MROWS;
    float m   = s * invM;
    float var = q * invM - m * m;
    float a   = gamma[c] * rsqrtf(var + BN_EPS);
    g_stats[(size_t)layer * 1024 + c]       = a;
    g_stats[(size_t)layer * 1024 + 512 + c] = beta[c] - m * a;
}

// ============ kernel 4a: BN + GELU -> split fp16 into g_A2 =================
__global__ __launch_bounds__(256)
void bn_gelu_split(const float* __restrict__ H)
{
    const size_t idx = (size_t)blockIdx.x * blockDim.x + threadIdx.x;
    const size_t total = (size_t)MROWS * 512 / 4;
    if (idx >= total) return;
    const int c0 = (int)((idx & 127) * 4);
    const size_t row = idx >> 7;
    const float* st = g_stats;   // layer 0

    float4 v = ((const float4*)H)[idx];
    float o[4] = {v.x, v.y, v.z, v.w};
    #pragma unroll
    for (int j = 0; j < 4; ++j) {
        int c = c0 + j;
        float y = fmaf(o[j], st[c], st[512 + c]);
        o[j] = gelu_f(y);
    }
    wsplit4(g_A2 + row * (2 * DH), DH, c0, make_float4(o[0], o[1], o[2], o[3]));
}

// ============ kernel 4b: BN + GELU in place (final output) =================
__global__ __launch_bounds__(256)
void bn_gelu_inplace(float* __restrict__ H)
{
    const size_t idx = (size_t)blockIdx.x * blockDim.x + threadIdx.x;
    const size_t total = (size_t)MROWS * 512 / 4;
    if (idx >= total) return;
    const int c0 = (int)((idx & 127) * 4);
    const float* st = g_stats + 1024;  // layer 1

    float4 v = ((const float4*)H)[idx];
    float o[4] = {v.x, v.y, v.z, v.w};
    #pragma unroll
    for (int j = 0; j < 4; ++j) {
        int c = c0 + j;
        float y = fmaf(o[j], st[c], st[512 + c]);
        o[j] = gelu_f(y);
    }
    ((float4*)H)[idx] = make_float4(o[0], o[1], o[2], o[3]);
}

// ============================ launcher =====================================
extern "C" void kernel_launch(void* const* d_in, const int* in_sizes, int n_in,
                              void* d_out, int out_size)
{
    const float* sxyz = (const float*)d_in[0];
    const float* spf  = (const float*)d_in[1];
    const float* xyz  = (const float*)d_in[2];
    const float* pf   = (const float*)d_in[3];
    const float* W1   = (const float*)d_in[4];
    const float* g1   = (const float*)d_in[5];
    const float* b1   = (const float*)d_in[6];
    const float* W2   = (const float*)d_in[7];
    const float* g2   = (const float*)d_in[8];
    const float* b2   = (const float*)d_in[9];
    float* out = (float*)d_out;

    __half *pA1, *pA2, *pB1, *pB2;
    float *pH, *pPart;
    cudaGetSymbolAddress((void**)&pA1, g_A1);
    cudaGetSymbolAddress((void**)&pA2, g_A2);
    cudaGetSymbolAddress((void**)&pB1, g_B1);
    cudaGetSymbolAddress((void**)&pB2, g_B2);
    cudaGetSymbolAddress((void**)&pH,  g_H);
    cudaGetSymbolAddress((void**)&pPart, g_part);

    cudaFuncSetAttribute(mma_gemm, cudaFuncAttributeMaxDynamicSharedMemorySize, GEMM_SMEM);

    // 0) weight transpose + hi cast
    wsplit_kernel<<<(DIN * DH + 255) / 256, 256>>>(W1, pB1, DIN, DH);
    wsplit_kernel<<<(DH * DOUT + 255) / 256, 256>>>(W2, pB2, DH, DOUT);

    // 1) 3-NN interpolation + concat + split -> g_A1 [65536, 768] fp16
    interp_kernel<<<dim3(NPTS / 256, BATCH), 256>>>(sxyz, spf, xyz, pf);

    // 2) GEMM1 (HMMA, fused stats): K = 384
    mma_gemm<<<dim3(DH / 128, MROWS / 128), 256, GEMM_SMEM>>>(pA1, pB1, pH, pPart, DIN);

    // 3) stats reduce (folded BN coeffs) + BN+GELU -> split fp16 g_A2
    colstats_mid<<<32, 512>>>();
    colstats_final<<<1, 512>>>(g1, b1, 0);
    bn_gelu_split<<<(MROWS * 512 / 4 + 255) / 256, 256>>>(pH);

    // 4) GEMM2 (HMMA, fused stats): K = 512
    mma_gemm<<<dim3(DOUT / 128, MROWS / 128), 256, GEMM_SMEM>>>(pA2, pB2, out, pPart, DH);

    // 5) stats reduce + BN+GELU in place on out
    colstats_mid<<<32, 512>>>();
    colstats_final<<<1, 512>>>(g2, b2, 1);
    bn_gelu_inplace<<<(MROWS * 512 / 4 + 255) / 256, 256>>>(out);
}